// round 8
// baseline (speedup 1.0000x reference)
#include <cuda_runtime.h>

#define IS      256
#define TILE    16
#define NTILEX  (IS / TILE)          // 16
#define NTILES  (NTILEX * NTILEX)    // 256
#define NSLICE  8
#define CHUNK   128
#define RTHREADS 128
#define NF_MAX  24000
#define NBINS   256
#define KRANGE  1.6f                 // key quantization range in zn units
#define FARV    100.0f
#define NEARV   0.1f

// prep output (face-indexed, unsorted)
__device__ float4 u_e0[NF_MAX], u_e1[NF_MAX], u_e2[NF_MAX], u_bb[NF_MAX], u_zp[NF_MAX];
__device__ int    u_bin[NF_MAX];
// sorted-by-depth face data (permute output) + monotone key floor
__device__ float4 g_e0[NF_MAX], g_e1[NF_MAX], g_e2[NF_MAX], g_bb[NF_MAX], g_zp[NF_MAX];
__device__ int    g_idx[NF_MAX];
__device__ float  g_key[NF_MAX];
__device__ int    g_B[NTILES];       // per-tile depth bound (float bits, atomicMin)

__global__ void prep_kernel(const float* __restrict__ verts,
                            const void*  __restrict__ facesp,
                            const float* __restrict__ Km,
                            const float* __restrict__ Rm,
                            const float* __restrict__ tm,
                            const int*   __restrict__ oszp,
                            int NF, int NV,
                            int* __restrict__ outi, int outn)
{
    int f = blockIdx.x * blockDim.x + threadIdx.x;
    int nth = gridDim.x * blockDim.x;

    // fold output + bound init into this launch (saves a standalone kernel)
    for (int i = f; i < outn; i += nth) outi[i] = __float_as_int(FARV);
    for (int i = f; i < NTILES; i += nth) g_B[i] = __float_as_int(FARV);

    if (f >= NF) return;

    // robust orig_size read (int32 / int64-low-word / float32); nullptr -> 224
    float os = 224.0f;
    if (oszp) {
        int iv = oszp[0];
        if (iv > 0 && iv < 1000000) os = (float)iv;
        else {
            float fv = __int_as_float(iv);
            if (fv > 0.0f && fv < 1000000.0f) os = fv;
        }
    }

    // dtype sniff: int64 indices in [0,NV) have zero hi-words (L1 broadcast reads)
    const int* f32 = (const int*)facesp;
    int oddbits = 0;
#pragma unroll
    for (int i = 1; i < 16; i += 2) oddbits |= f32[i];
    const bool is64 = (oddbits == 0);
    const long long* f64 = (const long long*)facesp;

    float fx = Km[0], fy = Km[4], cx = Km[2], cy = Km[5];

    float x[3], y[3], z[3];
#pragma unroll
    for (int c = 0; c < 3; c++) {
        long long vi = is64 ? f64[f * 3 + c] : (long long)f32[f * 3 + c];
        if (vi < 0) vi = 0;
        if (vi >= NV) vi = NV - 1;
        float vx = verts[vi * 3 + 0];
        float vy = verts[vi * 3 + 1];
        float vz = verts[vi * 3 + 2];
        float X = Rm[0] * vx + Rm[1] * vy + Rm[2] * vz + tm[0];
        float Y = Rm[3] * vx + Rm[4] * vy + Rm[5] * vz + tm[1];
        float Z = Rm[6] * vx + Rm[7] * vy + Rm[8] * vz + tm[2];
        float u = fx * X + cx;
        float w = fy * Y + cy;
        x[c] = 2.0f * u / os - 1.0f;
        y[c] = -(2.0f * w / os - 1.0f);
        z[c] = Z;
    }

    float A0 = y[1] - y[2], B0 = x[2] - x[1], C0 = x[1] * y[2] - x[2] * y[1];
    float A1 = y[2] - y[0], B1 = x[0] - x[2], C1 = x[2] * y[0] - x[0] * y[2];
    float A2 = y[0] - y[1], B2 = x[1] - x[0], C2 = x[0] * y[1] - x[1] * y[0];
    float area = C0 + C1 + C2;

    if (fabsf(area) <= 1e-10f) {
        u_bb[f] = make_float4(2.0f, -2.0f, 2.0f, -2.0f);
        u_e0[f] = make_float4(0, 0, 0, 0);
        u_e1[f] = make_float4(0, 0, 0, 0);
        u_e2[f] = make_float4(0, 0, 0, 0);
        u_zp[f] = make_float4(0, 0, 0, 0);
        u_bin[f] = NBINS - 1;
        return;
    }

    float s = (area > 0.0f) ? 1.0f : -1.0f;
    A0 *= s; B0 *= s; C0 *= s;
    A1 *= s; B1 *= s; C1 *= s;
    A2 *= s; B2 *= s; C2 *= s;
    float inv = 1.0f / (s * area);

    float Pa = (A0 * z[0] + A1 * z[1] + A2 * z[2]) * inv;
    float Pb = (B0 * z[0] + B1 * z[1] + B2 * z[2]) * inv;
    float Pc = (C0 * z[0] + C1 * z[1] + C2 * z[2]) * inv;

    u_e0[f] = make_float4(A0, B0, C0, Pa);
    u_e1[f] = make_float4(A1, B1, C1, Pb);
    u_e2[f] = make_float4(A2, B2, C2, Pc);
    u_zp[f] = make_float4(Pa, Pb, Pc, 0.0f);

    float4 bb;
    bb.x = fminf(x[0], fminf(x[1], x[2]));
    bb.y = fmaxf(x[0], fmaxf(x[1], x[2]));
    bb.z = fminf(y[0], fminf(y[1], y[2]));
    bb.w = fmaxf(y[0], fmaxf(y[1], y[2]));
    u_bb[f] = bb;

    float znmin = fminf(z[0], fminf(z[1], z[2])) - NEARV;
    int bin = (int)(znmin * (NBINS / KRANGE));
    u_bin[f] = max(0, min(NBINS - 1, bin));
}

// Single block: smem histogram -> prefix -> index permutation + key floor.
__global__ __launch_bounds__(1024)
void sortidx_kernel(int NF)
{
    __shared__ int h[NBINS];
    __shared__ int tmp[NBINS];
    __shared__ int st[NBINS];
    int t = threadIdx.x;

    if (t < NBINS) h[t] = 0;
    __syncthreads();
    for (int f = t; f < NF; f += 1024) atomicAdd(&h[u_bin[f]], 1);
    __syncthreads();
    if (t < NBINS) tmp[t] = h[t];
    __syncthreads();
#pragma unroll
    for (int off = 1; off < NBINS; off <<= 1) {
        int v = 0;
        if (t < NBINS && t >= off) v = tmp[t - off];
        __syncthreads();
        if (t < NBINS) tmp[t] += v;
        __syncthreads();
    }
    if (t < NBINS) st[t] = tmp[t] - h[t];   // exclusive prefix
    __syncthreads();
    for (int f = t; f < NF; f += 1024) {
        int b = u_bin[f];
        int pos = atomicAdd(&st[b], 1);
        g_idx[pos] = f;
        g_key[pos] = b * (KRANGE / NBINS);   // monotone bucket floor
    }
}

// Full-chip data movement: gather-read u_*, coalesced-write sorted g_*.
__global__ void permute_kernel(int NF)
{
    int pos = blockIdx.x * blockDim.x + threadIdx.x;
    if (pos >= NF) return;
    int idx = g_idx[pos];
    float4 a = u_e0[idx], b = u_e1[idx], c = u_e2[idx], d = u_bb[idx], e = u_zp[idx];
    g_e0[pos] = a;
    g_e1[pos] = b;
    g_e2[pos] = c;
    g_bb[pos] = d;
    g_zp[pos] = e;
}

// grid: (256 tiles, NSLICE). block: 128 threads, 2 pixels per thread.
// thread j: tile row = j>>3 (0..15), pixels 2*(j&7), 2*(j&7)+1
__global__ __launch_bounds__(RTHREADS)
void raster_kernel(int* __restrict__ outi, int NF)
{
    __shared__ float4 s_e0[CHUNK];
    __shared__ float4 s_e1[CHUNK];
    __shared__ float4 s_e2[CHUNK];
    __shared__ int    s_n;
    __shared__ float  s_B;     // best local bound so far
    __shared__ float  s_Bm;    // merged (local, global) bound for this chunk
    __shared__ float  s_wmax[4];

    const int tileId = blockIdx.x;
    const int tx = tileId & (NTILEX - 1);
    const int ty = tileId >> 4;

    const int j    = threadIdx.x;
    const int row  = j >> 3;
    const int cg   = j & 7;
    const int gcol0 = tx * TILE + cg * 2;
    const int grow  = ty * TILE + row;

    const float scale = 2.0f / IS;
    const float px0 = (gcol0 + 0.5f) * scale - 1.0f;
    const float px1 = px0 + scale;
    const float py  = 1.0f - (grow + 0.5f) * scale;

    const float pxlo = (tx * TILE + 0.5f) * scale - 1.0f;
    const float pxhi = (tx * TILE + TILE - 0.5f) * scale - 1.0f;
    const float pyhi = 1.0f - (ty * TILE + 0.5f) * scale;
    const float pylo = 1.0f - (ty * TILE + TILE - 0.5f) * scale;
    const float tcx = 0.5f * (pxlo + pxhi), thx = 0.5f * (pxhi - pxlo);
    const float tcy = 0.5f * (pylo + pyhi), thy = 0.5f * (pyhi - pylo);

    if (j < 4) s_wmax[j] = FARV;
    if (j == 0) s_B = FARV;

    // accumulate min of zn = (zp - NEARV); restored at the end
    float d0 = FARV, d1 = FARV;

    for (int base = blockIdx.y * CHUNK; base < NF; base += NSLICE * CHUNK) {
        if (j == 0) {
            s_n = 0;
            float lb = fminf(s_B, fmaxf(fmaxf(s_wmax[0], s_wmax[1]),
                                        fmaxf(s_wmax[2], s_wmax[3])));
            s_B = lb;
            s_Bm = fminf(lb, __int_as_float(g_B[tileId]));
        }
        __syncthreads();
        const float B = s_Bm + 1e-5f;   // conservative slack vs FP re-expression

        // sorted stream: all remaining faces have zn_min >= g_key[base]
        if (g_key[base] > B) break;

        const int lim = min(base + CHUNK, NF);

        // cooperative filter (one face per thread): bbox -> z-min bound -> exact SAT
        {
            int f = base + j;
            bool pass = false;
            float4 e0, e1, e2;
            if (f < lim) {
                float4 bb = g_bb[f];
                if (bb.x <= pxhi && bb.y >= pxlo && bb.z <= pyhi && bb.w >= pylo) {
                    float4 zp4 = g_zp[f];
                    float zc  = fmaf(zp4.x, tcx, fmaf(zp4.y, tcy, zp4.z));
                    float zmn = zc - fmaf(fabsf(zp4.x), thx, fabsf(zp4.y) * thy) - NEARV;
                    if (zmn <= B) {
                        e0 = g_e0[f]; e1 = g_e1[f]; e2 = g_e2[f];
                        float w0m = fmaf(e0.x, tcx, fmaf(e0.y, tcy, e0.z)) +
                                    fmaf(fabsf(e0.x), thx, fabsf(e0.y) * thy);
                        float w1m = fmaf(e1.x, tcx, fmaf(e1.y, tcy, e1.z)) +
                                    fmaf(fabsf(e1.x), thx, fabsf(e1.y) * thy);
                        float w2m = fmaf(e2.x, tcx, fmaf(e2.y, tcy, e2.z)) +
                                    fmaf(fabsf(e2.x), thx, fabsf(e2.y) * thy);
                        pass = (fminf(w0m, fminf(w1m, w2m)) >= -1e-6f);
                    }
                }
            }
            unsigned m = __ballot_sync(0xffffffffu, pass);
            int lane = j & 31;
            int posw = 0;
            int cnt = __popc(m);
            if (lane == 0 && cnt) posw = atomicAdd(&s_n, cnt);
            posw = __shfl_sync(0xffffffffu, posw, 0);
            if (pass) {
                int p = posw + __popc(m & ((1u << lane) - 1u));
                s_e0[p] = e0; s_e1[p] = e1; s_e2[p] = e2;
            }
        }
        __syncthreads();

        const int n = s_n;
#pragma unroll 2
        for (int i = 0; i < n; i++) {
            float4 e0 = s_e0[i];
            float4 e1 = s_e1[i];
            float4 e2 = s_e2[i];
            float b0 = fmaf(e0.y, py, e0.z);
            float b1 = fmaf(e1.y, py, e1.z);
            float b2 = fmaf(e2.y, py, e2.z);
            float bz = fmaf(e1.w, py, e2.w) - NEARV;

            {
                float w0 = fmaf(e0.x, px0, b0);
                float w1 = fmaf(e1.x, px0, b1);
                float w2 = fmaf(e2.x, px0, b2);
                float zn = fmaf(e0.w, px0, bz);
                float mn = fminf(fminf(w0, w1), fminf(w2, zn));
                if (mn >= 0.0f) d0 = fminf(d0, zn);
            }
            {
                float w0 = fmaf(e0.x, px1, b0);
                float w1 = fmaf(e1.x, px1, b1);
                float w2 = fmaf(e2.x, px1, b2);
                float zn = fmaf(e0.w, px1, bz);
                float mn = fminf(fminf(w0, w1), fminf(w2, zn));
                if (mn >= 0.0f) d1 = fminf(d1, zn);
            }
        }

        // update + publish tile depth bound (skip when nothing could have changed)
        if (n > 0) {
            float mx = fmaxf(d0, d1);
#pragma unroll
            for (int o = 16; o; o >>= 1)
                mx = fmaxf(mx, __shfl_xor_sync(0xffffffffu, mx, o));
            if ((j & 31) == 0) s_wmax[j >> 5] = mx;
            __syncthreads();
            if (j == 0) {
                float nb = fminf(s_B, fmaxf(fmaxf(s_wmax[0], s_wmax[1]),
                                            fmaxf(s_wmax[2], s_wmax[3])));
                s_B = nb;
                atomicMin(&g_B[tileId], __float_as_int(nb));  // positive floats
            }
        }
    }

    d0 = fminf(d0 + NEARV, FARV);
    d1 = fminf(d1 + NEARV, FARV);
    int o = grow * IS + gcol0;
    atomicMin(&outi[o + 0], __float_as_int(d0));
    atomicMin(&outi[o + 1], __float_as_int(d1));
}

extern "C" void kernel_launch(void* const* d_in, const int* in_sizes, int n_in,
                              void* d_out, int out_size)
{
    const float* verts  = (const float*)d_in[0];
    const void*  facesp = d_in[1];
    const float* K      = (const float*)d_in[2];
    const float* R      = (const float*)d_in[3];
    const float* t      = (const float*)d_in[4];
    const int*   osz    = (n_in >= 6) ? (const int*)d_in[5] : nullptr;

    int NF = in_sizes[1] / 3;   // skip reversed-winding duplicates (identical coverage)
    if (NF > NF_MAX) NF = NF_MAX;
    int NV = in_sizes[0] / 3;

    int* outi = (int*)d_out;
    prep_kernel<<<(NF + 127) / 128, 128>>>(verts, facesp, K, R, t, osz, NF, NV,
                                           outi, out_size);
    sortidx_kernel<<<1, 1024>>>(NF);
    permute_kernel<<<(NF + 255) / 256, 256>>>(NF);

    dim3 grid(NTILES, NSLICE);
    raster_kernel<<<grid, RTHREADS>>>(outi, NF);
}

// round 9
// speedup vs baseline: 1.1826x; 1.1826x over previous
#include <cuda_runtime.h>

#define IS      256
#define TILE    16
#define NTILEX  (IS / TILE)          // 16
#define NTILES  (NTILEX * NTILEX)    // 256
#define NSLICE  16
#define CHUNK   128
#define RTHREADS 64
#define NF_MAX  24000
#define NBINS   256
#define KRANGE  1.6f                 // key quantization range in zn units
#define FARV    100.0f
#define NEARV   0.1f

// prep output (face-indexed, unsorted)
__device__ float4 u_e0[NF_MAX], u_e1[NF_MAX], u_e2[NF_MAX], u_bb[NF_MAX];
__device__ int    u_bin[NF_MAX];
// sorted-by-depth face data (permute output) + monotone key floor
__device__ float4 g_e0[NF_MAX], g_e1[NF_MAX], g_e2[NF_MAX], g_bb[NF_MAX];
__device__ int    g_idx[NF_MAX];
__device__ float  g_key[NF_MAX];
__device__ int    g_B[NTILES];       // per-tile depth bound (float bits, atomicMin)

__global__ void prep_kernel(const float* __restrict__ verts,
                            const void*  __restrict__ facesp,
                            const float* __restrict__ Km,
                            const float* __restrict__ Rm,
                            const float* __restrict__ tm,
                            const int*   __restrict__ oszp,
                            int NF, int NV,
                            int* __restrict__ outi, int outn)
{
    int f = blockIdx.x * blockDim.x + threadIdx.x;
    int nth = gridDim.x * blockDim.x;

    // fold output + bound init into this launch (saves a standalone kernel)
    for (int i = f; i < outn; i += nth) outi[i] = __float_as_int(FARV);
    for (int i = f; i < NTILES; i += nth) g_B[i] = __float_as_int(FARV);

    if (f >= NF) return;

    // robust orig_size read (int32 / int64-low-word / float32); nullptr -> 224
    float os = 224.0f;
    if (oszp) {
        int iv = oszp[0];
        if (iv > 0 && iv < 1000000) os = (float)iv;
        else {
            float fv = __int_as_float(iv);
            if (fv > 0.0f && fv < 1000000.0f) os = fv;
        }
    }

    // dtype sniff: int64 indices in [0,NV) have zero hi-words (L1 broadcast reads)
    const int* f32 = (const int*)facesp;
    int oddbits = 0;
#pragma unroll
    for (int i = 1; i < 16; i += 2) oddbits |= f32[i];
    const bool is64 = (oddbits == 0);
    const long long* f64 = (const long long*)facesp;

    float fx = Km[0], fy = Km[4], cx = Km[2], cy = Km[5];

    float x[3], y[3], z[3];
#pragma unroll
    for (int c = 0; c < 3; c++) {
        long long vi = is64 ? f64[f * 3 + c] : (long long)f32[f * 3 + c];
        if (vi < 0) vi = 0;
        if (vi >= NV) vi = NV - 1;
        float vx = verts[vi * 3 + 0];
        float vy = verts[vi * 3 + 1];
        float vz = verts[vi * 3 + 2];
        float X = Rm[0] * vx + Rm[1] * vy + Rm[2] * vz + tm[0];
        float Y = Rm[3] * vx + Rm[4] * vy + Rm[5] * vz + tm[1];
        float Z = Rm[6] * vx + Rm[7] * vy + Rm[8] * vz + tm[2];
        float u = fx * X + cx;
        float w = fy * Y + cy;
        x[c] = 2.0f * u / os - 1.0f;
        y[c] = -(2.0f * w / os - 1.0f);
        z[c] = Z;
    }

    float A0 = y[1] - y[2], B0 = x[2] - x[1], C0 = x[1] * y[2] - x[2] * y[1];
    float A1 = y[2] - y[0], B1 = x[0] - x[2], C1 = x[2] * y[0] - x[0] * y[2];
    float A2 = y[0] - y[1], B2 = x[1] - x[0], C2 = x[0] * y[1] - x[1] * y[0];
    float area = C0 + C1 + C2;

    if (fabsf(area) <= 1e-10f) {
        u_bb[f] = make_float4(2.0f, -2.0f, 2.0f, -2.0f);  // empty bbox -> never passes
        u_e0[f] = make_float4(0, 0, 0, 0);
        u_e1[f] = make_float4(0, 0, 0, 0);
        u_e2[f] = make_float4(0, 0, 0, 0);
        u_bin[f] = NBINS - 1;
        return;
    }

    float s = (area > 0.0f) ? 1.0f : -1.0f;
    A0 *= s; B0 *= s; C0 *= s;
    A1 *= s; B1 *= s; C1 *= s;
    A2 *= s; B2 *= s; C2 *= s;
    float inv = 1.0f / (s * area);

    float Pa = (A0 * z[0] + A1 * z[1] + A2 * z[2]) * inv;
    float Pb = (B0 * z[0] + B1 * z[1] + B2 * z[2]) * inv;
    float Pc = (C0 * z[0] + C1 * z[1] + C2 * z[2]) * inv;

    u_e0[f] = make_float4(A0, B0, C0, Pa);
    u_e1[f] = make_float4(A1, B1, C1, Pb);
    u_e2[f] = make_float4(A2, B2, C2, Pc);

    float4 bb;
    bb.x = fminf(x[0], fminf(x[1], x[2]));
    bb.y = fmaxf(x[0], fmaxf(x[1], x[2]));
    bb.z = fminf(y[0], fminf(y[1], y[2]));
    bb.w = fmaxf(y[0], fmaxf(y[1], y[2]));
    u_bb[f] = bb;

    float znmin = fminf(z[0], fminf(z[1], z[2])) - NEARV;
    int bin = (int)(znmin * (NBINS / KRANGE));
    u_bin[f] = max(0, min(NBINS - 1, bin));
}

// Single block: smem histogram -> prefix -> index permutation + key floor.
__global__ __launch_bounds__(1024)
void sortidx_kernel(int NF)
{
    __shared__ int h[NBINS];
    __shared__ int tmp[NBINS];
    __shared__ int st[NBINS];
    int t = threadIdx.x;

    if (t < NBINS) h[t] = 0;
    __syncthreads();
    for (int f = t; f < NF; f += 1024) atomicAdd(&h[u_bin[f]], 1);
    __syncthreads();
    if (t < NBINS) tmp[t] = h[t];
    __syncthreads();
#pragma unroll
    for (int off = 1; off < NBINS; off <<= 1) {
        int v = 0;
        if (t < NBINS && t >= off) v = tmp[t - off];
        __syncthreads();
        if (t < NBINS) tmp[t] += v;
        __syncthreads();
    }
    if (t < NBINS) st[t] = tmp[t] - h[t];   // exclusive prefix
    __syncthreads();
    for (int f = t; f < NF; f += 1024) {
        int b = u_bin[f];
        int pos = atomicAdd(&st[b], 1);
        g_idx[pos] = f;
        g_key[pos] = b * (KRANGE / NBINS);   // monotone bucket floor
    }
}

// Data movement: one float4 per thread, threadIdx.y selects array (4x parallelism,
// g_idx read is an L1 broadcast across y).
__global__ void permute_kernel(int NF)
{
    int pos = blockIdx.x * 64 + threadIdx.x;
    if (pos >= NF) return;
    int idx = g_idx[pos];
    switch (threadIdx.y) {
        case 0: g_e0[pos] = u_e0[idx]; break;
        case 1: g_e1[pos] = u_e1[idx]; break;
        case 2: g_e2[pos] = u_e2[idx]; break;
        default: g_bb[pos] = u_bb[idx]; break;
    }
}

// grid: (256 tiles, NSLICE). block: 64 threads, 4 pixels per thread.
// thread j: tile row = j>>2 (0..15), pixels (j&3)*4 .. +3
__global__ __launch_bounds__(RTHREADS)
void raster_kernel(int* __restrict__ outi, int NF)
{
    __shared__ float4 s_e0[CHUNK];
    __shared__ float4 s_e1[CHUNK];
    __shared__ float4 s_e2[CHUNK];
    __shared__ int    s_n;
    __shared__ float  s_B;     // best local bound so far
    __shared__ float  s_Bm;    // merged (local, global) bound for this chunk
    __shared__ float  s_wmax[2];

    const int tileId = blockIdx.x;
    const int tx = tileId & (NTILEX - 1);
    const int ty = tileId >> 4;

    const int j    = threadIdx.x;
    const int row  = j >> 2;
    const int cg   = j & 3;
    const int gcol0 = tx * TILE + cg * 4;
    const int grow  = ty * TILE + row;

    const float scale = 2.0f / IS;
    const float px0 = (gcol0 + 0.5f) * scale - 1.0f;
    const float px1 = px0 + scale;
    const float px2 = px0 + 2.0f * scale;
    const float px3 = px0 + 3.0f * scale;
    const float py  = 1.0f - (grow + 0.5f) * scale;

    const float pxlo = (tx * TILE + 0.5f) * scale - 1.0f;
    const float pxhi = (tx * TILE + TILE - 0.5f) * scale - 1.0f;
    const float pyhi = 1.0f - (ty * TILE + 0.5f) * scale;
    const float pylo = 1.0f - (ty * TILE + TILE - 0.5f) * scale;
    const float tcx = 0.5f * (pxlo + pxhi), thx = 0.5f * (pxhi - pxlo);
    const float tcy = 0.5f * (pylo + pyhi), thy = 0.5f * (pyhi - pylo);

    if (j < 2) s_wmax[j] = FARV;
    if (j == 0) s_B = FARV;

    // accumulate min of zn = (zp - NEARV); restored at the end
    float d0 = FARV, d1 = FARV, d2 = FARV, d3 = FARV;

    for (int base = blockIdx.y * CHUNK; base < NF; base += NSLICE * CHUNK) {
        if (j == 0) {
            s_n = 0;
            float lb = fminf(s_B, fmaxf(s_wmax[0], s_wmax[1]));
            s_B = lb;
            s_Bm = fminf(lb, __int_as_float(g_B[tileId]));
        }
        __syncthreads();
        const float B = s_Bm + 1e-5f;   // conservative slack vs FP re-expression

        // sorted stream: all remaining faces have zn_min >= g_key[base]
        if (g_key[base] > B) break;

        const int lim = min(base + CHUNK, NF);

        // branchless filter: 4 independent LDG.128 per face, then pure predicate math
        // (bbox AND tile-SAT AND tile-z-min <= bound). Max MLP, no dependent-load chain.
#pragma unroll
        for (int off = 0; off < CHUNK; off += RTHREADS) {
            int f = base + off + j;
            bool pass = false;
            float4 e0, e1, e2;
            if (f < lim) {
                float4 bb = g_bb[f];
                e0 = g_e0[f]; e1 = g_e1[f]; e2 = g_e2[f];
                // max of edge fn over tile box; if < 0 the tile is fully outside
                float w0m = fmaf(e0.x, tcx, fmaf(e0.y, tcy, e0.z)) +
                            fmaf(fabsf(e0.x), thx, fabsf(e0.y) * thy);
                float w1m = fmaf(e1.x, tcx, fmaf(e1.y, tcy, e1.z)) +
                            fmaf(fabsf(e1.x), thx, fabsf(e1.y) * thy);
                float w2m = fmaf(e2.x, tcx, fmaf(e2.y, tcy, e2.z)) +
                            fmaf(fabsf(e2.x), thx, fabsf(e2.y) * thy);
                // min of depth plane over the tile box (zn units); Pa,Pb,Pc = e*.w
                float zc  = fmaf(e0.w, tcx, fmaf(e1.w, tcy, e2.w));
                float zmn = zc - fmaf(fabsf(e0.w), thx, fabsf(e1.w) * thy) - NEARV;
                pass = (fminf(w0m, fminf(w1m, w2m)) >= -1e-6f)
                     & (bb.x <= pxhi) & (bb.y >= pxlo)
                     & (bb.z <= pyhi) & (bb.w >= pylo)
                     & (zmn <= B);
            }
            unsigned m = __ballot_sync(0xffffffffu, pass);
            int lane = j & 31;
            int posw = 0;
            int cnt = __popc(m);
            if (lane == 0 && cnt) posw = atomicAdd(&s_n, cnt);
            posw = __shfl_sync(0xffffffffu, posw, 0);
            if (pass) {
                int p = posw + __popc(m & ((1u << lane) - 1u));
                s_e0[p] = e0; s_e1[p] = e1; s_e2[p] = e2;
            }
        }
        __syncthreads();

        const int n = s_n;
#pragma unroll 2
        for (int i = 0; i < n; i++) {
            float4 e0 = s_e0[i];
            float4 e1 = s_e1[i];
            float4 e2 = s_e2[i];
            float b0 = fmaf(e0.y, py, e0.z);
            float b1 = fmaf(e1.y, py, e1.z);
            float b2 = fmaf(e2.y, py, e2.z);
            float bz = fmaf(e1.w, py, e2.w) - NEARV;

            {
                float w0 = fmaf(e0.x, px0, b0);
                float w1 = fmaf(e1.x, px0, b1);
                float w2 = fmaf(e2.x, px0, b2);
                float zn = fmaf(e0.w, px0, bz);
                float mn = fminf(fminf(w0, w1), fminf(w2, zn));
                if (mn >= 0.0f) d0 = fminf(d0, zn);
            }
            {
                float w0 = fmaf(e0.x, px1, b0);
                float w1 = fmaf(e1.x, px1, b1);
                float w2 = fmaf(e2.x, px1, b2);
                float zn = fmaf(e0.w, px1, bz);
                float mn = fminf(fminf(w0, w1), fminf(w2, zn));
                if (mn >= 0.0f) d1 = fminf(d1, zn);
            }
            {
                float w0 = fmaf(e0.x, px2, b0);
                float w1 = fmaf(e1.x, px2, b1);
                float w2 = fmaf(e2.x, px2, b2);
                float zn = fmaf(e0.w, px2, bz);
                float mn = fminf(fminf(w0, w1), fminf(w2, zn));
                if (mn >= 0.0f) d2 = fminf(d2, zn);
            }
            {
                float w0 = fmaf(e0.x, px3, b0);
                float w1 = fmaf(e1.x, px3, b1);
                float w2 = fmaf(e2.x, px3, b2);
                float zn = fmaf(e0.w, px3, bz);
                float mn = fminf(fminf(w0, w1), fminf(w2, zn));
                if (mn >= 0.0f) d3 = fminf(d3, zn);
            }
        }

        // update + publish tile depth bound (skip when nothing could have changed)
        if (n > 0) {
            float mx = fmaxf(fmaxf(d0, d1), fmaxf(d2, d3));
#pragma unroll
            for (int o = 16; o; o >>= 1)
                mx = fmaxf(mx, __shfl_xor_sync(0xffffffffu, mx, o));
            if ((j & 31) == 0) s_wmax[j >> 5] = mx;
            __syncthreads();
            if (j == 0) {
                float nb = fminf(s_B, fmaxf(s_wmax[0], s_wmax[1]));
                s_B = nb;
                atomicMin(&g_B[tileId], __float_as_int(nb));  // positive floats
            }
        }
    }

    d0 = fminf(d0 + NEARV, FARV);
    d1 = fminf(d1 + NEARV, FARV);
    d2 = fminf(d2 + NEARV, FARV);
    d3 = fminf(d3 + NEARV, FARV);
    int o = grow * IS + gcol0;
    atomicMin(&outi[o + 0], __float_as_int(d0));
    atomicMin(&outi[o + 1], __float_as_int(d1));
    atomicMin(&outi[o + 2], __float_as_int(d2));
    atomicMin(&outi[o + 3], __float_as_int(d3));
}

extern "C" void kernel_launch(void* const* d_in, const int* in_sizes, int n_in,
                              void* d_out, int out_size)
{
    const float* verts  = (const float*)d_in[0];
    const void*  facesp = d_in[1];
    const float* K      = (const float*)d_in[2];
    const float* R      = (const float*)d_in[3];
    const float* t      = (const float*)d_in[4];
    const int*   osz    = (n_in >= 6) ? (const int*)d_in[5] : nullptr;

    int NF = in_sizes[1] / 3;   // skip reversed-winding duplicates (identical coverage)
    if (NF > NF_MAX) NF = NF_MAX;
    int NV = in_sizes[0] / 3;

    int* outi = (int*)d_out;
    prep_kernel<<<(NF + 63) / 64, 64>>>(verts, facesp, K, R, t, osz, NF, NV,
                                        outi, out_size);
    sortidx_kernel<<<1, 1024>>>(NF);
    dim3 pb(64, 4);
    permute_kernel<<<(NF + 63) / 64, pb>>>(NF);

    dim3 grid(NTILES, NSLICE);
    raster_kernel<<<grid, RTHREADS>>>(outi, NF);
}

// round 10
// speedup vs baseline: 1.3760x; 1.1635x over previous
#include <cuda_runtime.h>

#define IS      256
#define TILE    16
#define NTILEX  (IS / TILE)          // 16
#define NTILES  (NTILEX * NTILEX)    // 256
#define NSLICE  16
#define CHUNK   128
#define RTHREADS 64
#define SBLK    512
#define NF_MAX  24000
#define NBINS   256
#define KRANGE  1.0f                 // key quantization range in zn units
#define FARV    100.0f
#define NEARV   0.1f

// prep output (face-indexed, unsorted). e2.w stores (Pc - NEARV).
__device__ float4 u_e0[NF_MAX], u_e1[NF_MAX], u_e2[NF_MAX], u_bb[NF_MAX];
__device__ int    u_bin[NF_MAX];
// sorted-by-depth face data (permute output) + monotone key floor
__device__ float4 g_e0[NF_MAX], g_e1[NF_MAX], g_e2[NF_MAX], g_bb[NF_MAX];
__device__ int    g_idx[NF_MAX];
__device__ float  g_key[NF_MAX];
__device__ int    g_B[NTILES];       // per-tile depth bound (float bits, atomicMin)
__device__ int    g_hist[NBINS];     // zero at entry (module load / end of permute)
__device__ int    g_cursor[NBINS];   // zero at entry (module load / end of permute)

__global__ void prep_kernel(const float* __restrict__ verts,
                            const void*  __restrict__ facesp,
                            const float* __restrict__ Km,
                            const float* __restrict__ Rm,
                            const float* __restrict__ tm,
                            const int*   __restrict__ oszp,
                            int NF, int NV,
                            int* __restrict__ outi, int outn)
{
    int f = blockIdx.x * blockDim.x + threadIdx.x;
    int nth = gridDim.x * blockDim.x;

    // fold output + bound init into this launch
    for (int i = f; i < outn; i += nth) outi[i] = __float_as_int(FARV);
    for (int i = f; i < NTILES; i += nth) g_B[i] = __float_as_int(FARV);

    if (f >= NF) return;

    // robust orig_size read (int32 / int64-low-word / float32); nullptr -> 224
    float os = 224.0f;
    if (oszp) {
        int iv = oszp[0];
        if (iv > 0 && iv < 1000000) os = (float)iv;
        else {
            float fv = __int_as_float(iv);
            if (fv > 0.0f && fv < 1000000.0f) os = fv;
        }
    }

    // dtype sniff: int64 indices in [0,NV) have zero hi-words (L1 broadcast reads)
    const int* f32 = (const int*)facesp;
    int oddbits = 0;
#pragma unroll
    for (int i = 1; i < 16; i += 2) oddbits |= f32[i];
    const bool is64 = (oddbits == 0);
    const long long* f64 = (const long long*)facesp;

    float fx = Km[0], fy = Km[4], cx = Km[2], cy = Km[5];

    float x[3], y[3], z[3];
#pragma unroll
    for (int c = 0; c < 3; c++) {
        long long vi = is64 ? f64[f * 3 + c] : (long long)f32[f * 3 + c];
        if (vi < 0) vi = 0;
        if (vi >= NV) vi = NV - 1;
        float vx = verts[vi * 3 + 0];
        float vy = verts[vi * 3 + 1];
        float vz = verts[vi * 3 + 2];
        float X = Rm[0] * vx + Rm[1] * vy + Rm[2] * vz + tm[0];
        float Y = Rm[3] * vx + Rm[4] * vy + Rm[5] * vz + tm[1];
        float Z = Rm[6] * vx + Rm[7] * vy + Rm[8] * vz + tm[2];
        float u = fx * X + cx;
        float w = fy * Y + cy;
        x[c] = 2.0f * u / os - 1.0f;
        y[c] = -(2.0f * w / os - 1.0f);
        z[c] = Z;
    }

    float A0 = y[1] - y[2], B0 = x[2] - x[1], C0 = x[1] * y[2] - x[2] * y[1];
    float A1 = y[2] - y[0], B1 = x[0] - x[2], C1 = x[2] * y[0] - x[0] * y[2];
    float A2 = y[0] - y[1], B2 = x[1] - x[0], C2 = x[0] * y[1] - x[1] * y[0];
    float area = C0 + C1 + C2;

    if (fabsf(area) <= 1e-10f) {
        u_bb[f] = make_float4(2.0f, -2.0f, 2.0f, -2.0f);  // empty bbox -> never passes
        u_e0[f] = make_float4(0, 0, 0, 0);
        u_e1[f] = make_float4(0, 0, 0, 0);
        u_e2[f] = make_float4(0, 0, 0, 0);
        u_bin[f] = NBINS - 1;
        atomicAdd(&g_hist[NBINS - 1], 1);
        return;
    }

    float s = (area > 0.0f) ? 1.0f : -1.0f;
    A0 *= s; B0 *= s; C0 *= s;
    A1 *= s; B1 *= s; C1 *= s;
    A2 *= s; B2 *= s; C2 *= s;
    float inv = 1.0f / (s * area);

    float Pa = (A0 * z[0] + A1 * z[1] + A2 * z[2]) * inv;
    float Pb = (B0 * z[0] + B1 * z[1] + B2 * z[2]) * inv;
    float Pc = (C0 * z[0] + C1 * z[1] + C2 * z[2]) * inv;

    u_e0[f] = make_float4(A0, B0, C0, Pa);
    u_e1[f] = make_float4(A1, B1, C1, Pb);
    u_e2[f] = make_float4(A2, B2, C2, Pc - NEARV);   // near-test pre-folded

    float4 bb;
    bb.x = fminf(x[0], fminf(x[1], x[2]));
    bb.y = fmaxf(x[0], fmaxf(x[1], x[2]));
    bb.z = fminf(y[0], fminf(y[1], y[2]));
    bb.w = fmaxf(y[0], fmaxf(y[1], y[2]));
    u_bb[f] = bb;

    float znmin = fminf(z[0], fminf(z[1], z[2])) - NEARV;
    int bin = (int)(znmin * (NBINS / KRANGE));
    bin = max(0, min(NBINS - 1, bin));
    u_bin[f] = bin;
    atomicAdd(&g_hist[bin], 1);
}

// Multi-block counting-sort scatter. Each block: redundant smem prefix of the
// global histogram, smem-rank of its own 512 faces, one cursor atomic per
// non-empty bin, then position writes. Order within a bin is irrelevant.
__global__ __launch_bounds__(SBLK)
void scatter_kernel(int NF)
{
    __shared__ int pref[NBINS];   // becomes inclusive prefix
    __shared__ int hg[NBINS];     // global hist copy
    __shared__ int h2[NBINS];     // block-local counts
    __shared__ int base2[NBINS];  // block's reserved base within each bin

    int t = threadIdx.x;
    int f = blockIdx.x * SBLK + t;

    if (t < NBINS) {
        int h = g_hist[t];
        hg[t] = h;
        pref[t] = h;
        h2[t] = 0;
    }
    __syncthreads();
#pragma unroll
    for (int off = 1; off < NBINS; off <<= 1) {
        int v = 0;
        if (t < NBINS && t >= off) v = pref[t - off];
        __syncthreads();
        if (t < NBINS) pref[t] += v;
        __syncthreads();
    }

    int bin = 0, rank = 0;
    if (f < NF) {
        bin = u_bin[f];
        rank = atomicAdd(&h2[bin], 1);
    }
    __syncthreads();
    if (t < NBINS && h2[t] > 0) base2[t] = atomicAdd(&g_cursor[t], h2[t]);
    __syncthreads();
    if (f < NF) {
        int pos = (pref[bin] - hg[bin]) + base2[bin] + rank;
        g_idx[pos] = f;
        g_key[pos] = bin * (KRANGE / NBINS);   // monotone bucket floor
    }
}

// Data movement: one float4 per thread, threadIdx.y selects array.
// Also resets g_hist/g_cursor so the next kernel_launch call starts clean.
__global__ void permute_kernel(int NF)
{
    if (blockIdx.x == 0) {
        int tid = threadIdx.y * 64 + threadIdx.x;
        if (tid < NBINS) { g_hist[tid] = 0; g_cursor[tid] = 0; }
    }
    int pos = blockIdx.x * 64 + threadIdx.x;
    if (pos >= NF) return;
    int idx = g_idx[pos];
    switch (threadIdx.y) {
        case 0: g_e0[pos] = u_e0[idx]; break;
        case 1: g_e1[pos] = u_e1[idx]; break;
        case 2: g_e2[pos] = u_e2[idx]; break;
        default: g_bb[pos] = u_bb[idx]; break;
    }
}

// grid: (256 tiles, NSLICE). block: 64 threads, 4 pixels per thread.
__global__ __launch_bounds__(RTHREADS)
void raster_kernel(int* __restrict__ outi, int NF)
{
    __shared__ float4 s_e[CHUNK * 3];   // interleaved e0,e1,e2 per face
    __shared__ int    s_n;
    __shared__ float  s_B;
    __shared__ float  s_Bm;
    __shared__ float  s_wmax[2];

    const int tileId = blockIdx.x;
    const int tx = tileId & (NTILEX - 1);
    const int ty = tileId >> 4;

    const int j    = threadIdx.x;
    const int row  = j >> 2;
    const int cg   = j & 3;
    const int gcol0 = tx * TILE + cg * 4;
    const int grow  = ty * TILE + row;

    const float scale = 2.0f / IS;
    const float px0 = (gcol0 + 0.5f) * scale - 1.0f;
    const float px1 = px0 + scale;
    const float px2 = px0 + 2.0f * scale;
    const float px3 = px0 + 3.0f * scale;
    const float py  = 1.0f - (grow + 0.5f) * scale;

    const float pxlo = (tx * TILE + 0.5f) * scale - 1.0f;
    const float pxhi = (tx * TILE + TILE - 0.5f) * scale - 1.0f;
    const float pyhi = 1.0f - (ty * TILE + 0.5f) * scale;
    const float pylo = 1.0f - (ty * TILE + TILE - 0.5f) * scale;
    const float tcx = 0.5f * (pxlo + pxhi), thx = 0.5f * (pxhi - pxlo);
    const float tcy = 0.5f * (pylo + pyhi), thy = 0.5f * (pyhi - pylo);

    if (j < 2) s_wmax[j] = FARV;
    if (j == 0) s_B = FARV;

    // accumulate min of zn = (zp - NEARV); restored at the end
    float d0 = FARV, d1 = FARV, d2 = FARV, d3 = FARV;

    for (int base = blockIdx.y * CHUNK; base < NF; base += NSLICE * CHUNK) {
        if (j == 0) {
            s_n = 0;
            float lb = fminf(s_B, fmaxf(s_wmax[0], s_wmax[1]));
            s_B = lb;
            s_Bm = fminf(lb, __int_as_float(g_B[tileId]));
        }
        __syncthreads();
        const float B = s_Bm + 1e-5f;   // conservative slack vs FP re-expression

        // sorted stream: all remaining faces have zn_min >= g_key[base]
        if (g_key[base] > B) break;

        const int lim = min(base + CHUNK, NF);

        // branchless filter: 4 independent LDG.128 per face, pure predicate math
#pragma unroll
        for (int off = 0; off < CHUNK; off += RTHREADS) {
            int f = base + off + j;
            bool pass = false;
            float4 e0, e1, e2;
            if (f < lim) {
                float4 bb = g_bb[f];
                e0 = g_e0[f]; e1 = g_e1[f]; e2 = g_e2[f];
                float w0m = fmaf(e0.x, tcx, fmaf(e0.y, tcy, e0.z)) +
                            fmaf(fabsf(e0.x), thx, fabsf(e0.y) * thy);
                float w1m = fmaf(e1.x, tcx, fmaf(e1.y, tcy, e1.z)) +
                            fmaf(fabsf(e1.x), thx, fabsf(e1.y) * thy);
                float w2m = fmaf(e2.x, tcx, fmaf(e2.y, tcy, e2.z)) +
                            fmaf(fabsf(e2.x), thx, fabsf(e2.y) * thy);
                // min of depth plane over tile (zn units; e2.w has -NEAR folded)
                float zc  = fmaf(e0.w, tcx, fmaf(e1.w, tcy, e2.w));
                float zmn = zc - fmaf(fabsf(e0.w), thx, fabsf(e1.w) * thy);
                pass = (fminf(w0m, fminf(w1m, w2m)) >= -1e-6f)
                     & (bb.x <= pxhi) & (bb.y >= pxlo)
                     & (bb.z <= pyhi) & (bb.w >= pylo)
                     & (zmn <= B);
            }
            unsigned m = __ballot_sync(0xffffffffu, pass);
            int lane = j & 31;
            int posw = 0;
            int cnt = __popc(m);
            if (lane == 0 && cnt) posw = atomicAdd(&s_n, cnt);
            posw = __shfl_sync(0xffffffffu, posw, 0);
            if (pass) {
                int p = 3 * (posw + __popc(m & ((1u << lane) - 1u)));
                s_e[p + 0] = e0; s_e[p + 1] = e1; s_e[p + 2] = e2;
            }
        }
        __syncthreads();

        const int n = s_n;
#pragma unroll 2
        for (int i = 0; i < n; i++) {
            float4 e0 = s_e[3 * i + 0];
            float4 e1 = s_e[3 * i + 1];
            float4 e2 = s_e[3 * i + 2];
            float b0 = fmaf(e0.y, py, e0.z);
            float b1 = fmaf(e1.y, py, e1.z);
            float b2 = fmaf(e2.y, py, e2.z);
            float bz = fmaf(e1.w, py, e2.w);   // -NEAR pre-folded

            {
                float w0 = fmaf(e0.x, px0, b0);
                float w1 = fmaf(e1.x, px0, b1);
                float w2 = fmaf(e2.x, px0, b2);
                float zn = fmaf(e0.w, px0, bz);
                float mn = fminf(fminf(w0, w1), fminf(w2, zn));
                if (mn >= 0.0f) d0 = fminf(d0, zn);
            }
            {
                float w0 = fmaf(e0.x, px1, b0);
                float w1 = fmaf(e1.x, px1, b1);
                float w2 = fmaf(e2.x, px1, b2);
                float zn = fmaf(e0.w, px1, bz);
                float mn = fminf(fminf(w0, w1), fminf(w2, zn));
                if (mn >= 0.0f) d1 = fminf(d1, zn);
            }
            {
                float w0 = fmaf(e0.x, px2, b0);
                float w1 = fmaf(e1.x, px2, b1);
                float w2 = fmaf(e2.x, px2, b2);
                float zn = fmaf(e0.w, px2, bz);
                float mn = fminf(fminf(w0, w1), fminf(w2, zn));
                if (mn >= 0.0f) d2 = fminf(d2, zn);
            }
            {
                float w0 = fmaf(e0.x, px3, b0);
                float w1 = fmaf(e1.x, px3, b1);
                float w2 = fmaf(e2.x, px3, b2);
                float zn = fmaf(e0.w, px3, bz);
                float mn = fminf(fminf(w0, w1), fminf(w2, zn));
                if (mn >= 0.0f) d3 = fminf(d3, zn);
            }
        }

        // update + publish tile depth bound (skip when nothing changed)
        if (n > 0) {
            float mx = fmaxf(fmaxf(d0, d1), fmaxf(d2, d3));
#pragma unroll
            for (int o = 16; o; o >>= 1)
                mx = fmaxf(mx, __shfl_xor_sync(0xffffffffu, mx, o));
            if ((j & 31) == 0) s_wmax[j >> 5] = mx;
            __syncthreads();
            if (j == 0) {
                float nb = fminf(s_B, fmaxf(s_wmax[0], s_wmax[1]));
                s_B = nb;
                atomicMin(&g_B[tileId], __float_as_int(nb));  // positive floats
            }
        }
    }

    d0 = fminf(d0 + NEARV, FARV);
    d1 = fminf(d1 + NEARV, FARV);
    d2 = fminf(d2 + NEARV, FARV);
    d3 = fminf(d3 + NEARV, FARV);
    int o = grow * IS + gcol0;
    atomicMin(&outi[o + 0], __float_as_int(d0));
    atomicMin(&outi[o + 1], __float_as_int(d1));
    atomicMin(&outi[o + 2], __float_as_int(d2));
    atomicMin(&outi[o + 3], __float_as_int(d3));
}

extern "C" void kernel_launch(void* const* d_in, const int* in_sizes, int n_in,
                              void* d_out, int out_size)
{
    const float* verts  = (const float*)d_in[0];
    const void*  facesp = d_in[1];
    const float* K      = (const float*)d_in[2];
    const float* R      = (const float*)d_in[3];
    const float* t      = (const float*)d_in[4];
    const int*   osz    = (n_in >= 6) ? (const int*)d_in[5] : nullptr;

    int NF = in_sizes[1] / 3;   // skip reversed-winding duplicates (identical coverage)
    if (NF > NF_MAX) NF = NF_MAX;
    int NV = in_sizes[0] / 3;

    int* outi = (int*)d_out;
    prep_kernel<<<(NF + 63) / 64, 64>>>(verts, facesp, K, R, t, osz, NF, NV,
                                        outi, out_size);
    scatter_kernel<<<(NF + SBLK - 1) / SBLK, SBLK>>>(NF);
    dim3 pb(64, 4);
    permute_kernel<<<(NF + 63) / 64, pb>>>(NF);

    dim3 grid(NTILES, NSLICE);
    raster_kernel<<<grid, RTHREADS>>>(outi, NF);
}